// round 1
// baseline (speedup 1.0000x reference)
#include <cuda_runtime.h>
#include <cuda_bf16.h>
#include <cstdint>

#define DIMC 512
#define HIDC 1024
#define NBATCH 16
#define HH 64
#define WW 64
#define NPIX (NBATCH*HH*WW)   // 65536

// ---------------- scratch (device globals; no allocation allowed) -------------
__device__ __nv_bfloat16 g_h[(size_t)NPIX*DIMC];       // LN1 output
__device__ __nv_bfloat16 g_an[(size_t)NPIX*DIMC];      // row-normalized LN2 output (GEMM1 A)
__device__ __nv_bfloat16 g_hidden[(size_t)NPIX*HIDC];  // gelu(sim*si)  (GEMM2 A)
__device__ __nv_bfloat16 g_win[DIMC*HIDC];             // col-normalized proto_in
__device__ __nv_bfloat16 g_wout[HIDC*DIMC];            // col-normalized proto_out
__device__ float g_gp[NBATCH*DIMC];                    // per (b,c) sum of h over image
__device__ float g_rowsq[NPIX];                        // per-row sum of gelu^2

// ---------------- helpers ----------------------------------------------------
__device__ __forceinline__ float wredsum(float v) {
#pragma unroll
    for (int o = 16; o > 0; o >>= 1) v += __shfl_xor_sync(0xffffffffu, v, o);
    return v;
}

__device__ __forceinline__ float4 ld_bf4(const __nv_bfloat16* p) {
    uint2 u = *(const uint2*)p;
    __nv_bfloat162 lo = *(__nv_bfloat162*)&u.x;
    __nv_bfloat162 hi = *(__nv_bfloat162*)&u.y;
    return make_float4(__bfloat162float(lo.x), __bfloat162float(lo.y),
                       __bfloat162float(hi.x), __bfloat162float(hi.y));
}

__device__ __forceinline__ void st_bf4(__nv_bfloat16* p, float a, float b, float c, float d) {
    __nv_bfloat162 lo = __floats2bfloat162_rn(a, b);
    __nv_bfloat162 hi = __floats2bfloat162_rn(c, d);
    uint2 u;
    u.x = *(uint32_t*)&lo;
    u.y = *(uint32_t*)&hi;
    *(uint2*)p = u;
}

__device__ __forceinline__ float gelu_exact(float u) {
    return 0.5f * u * (1.0f + erff(u * 0.70710678118654752f));
}

// ---------------- K0: weight column-normalization -----------------------------
__global__ void k_norm_win(const float* __restrict__ p) {  // [DIMC, HIDC], normalize cols
    int j = blockIdx.x * blockDim.x + threadIdx.x;  // 0..HIDC-1
    float ss = 0.f;
    for (int i = 0; i < DIMC; i++) { float v = p[(size_t)i*HIDC + j]; ss += v*v; }
    float inv = 1.f / fmaxf(sqrtf(ss), 1e-12f);
    for (int i = 0; i < DIMC; i++)
        g_win[(size_t)i*HIDC + j] = __float2bfloat16(p[(size_t)i*HIDC + j] * inv);
}

__global__ void k_norm_wout(const float* __restrict__ p) {  // [HIDC, DIMC], normalize cols
    int j = blockIdx.x * blockDim.x + threadIdx.x;  // 0..DIMC-1
    float ss = 0.f;
    for (int i = 0; i < HIDC; i++) { float v = p[(size_t)i*DIMC + j]; ss += v*v; }
    float inv = 1.f / fmaxf(sqrtf(ss), 1e-12f);
    for (int i = 0; i < HIDC; i++)
        g_wout[(size_t)i*DIMC + j] = __float2bfloat16(p[(size_t)i*DIMC + j] * inv);
}

// ---------------- K1: LayerNorm1 -> g_h (bf16); also zero g_gp ----------------
// grid = 1024 blocks (one per (b,y) image row), 256 threads = 8 warps, warp=8 pixels
__global__ void k_ln1(const float* __restrict__ x, const float* __restrict__ w,
                      const float* __restrict__ bb) {
    int rowid = blockIdx.x;
    int warp = threadIdx.x >> 5, lane = threadIdx.x & 31;
    if (rowid == 0) {
        for (int i = threadIdx.x; i < NBATCH*DIMC; i += 256) g_gp[i] = 0.f;
    }
    int cb = lane * 4;
    float4 wv[4], bv[4];
#pragma unroll
    for (int i = 0; i < 4; i++) {
        wv[i] = *(const float4*)(w + cb + i*128);
        bv[i] = *(const float4*)(bb + cb + i*128);
    }
    for (int px = 0; px < 8; ++px) {
        size_t p = (size_t)rowid * 64 + warp * 8 + px;
        const float4* xp = (const float4*)(x + p * DIMC);
        float4 v[4];
        float s = 0.f, sq = 0.f;
#pragma unroll
        for (int i = 0; i < 4; i++) {
            v[i] = xp[lane + i*32];
            s  += v[i].x + v[i].y + v[i].z + v[i].w;
            sq += v[i].x*v[i].x + v[i].y*v[i].y + v[i].z*v[i].z + v[i].w*v[i].w;
        }
        s = wredsum(s); sq = wredsum(sq);
        float m = s * (1.f/512.f);
        float var = sq * (1.f/512.f) - m*m;
        float rstd = rsqrtf(var + 1e-5f);
        __nv_bfloat16* hp = g_h + p * DIMC;
#pragma unroll
        for (int i = 0; i < 4; i++) {
            float h0 = (v[i].x - m)*rstd*wv[i].x + bv[i].x;
            float h1 = (v[i].y - m)*rstd*wv[i].y + bv[i].y;
            float h2 = (v[i].z - m)*rstd*wv[i].z + bv[i].z;
            float h3 = (v[i].w - m)*rstd*wv[i].w + bv[i].w;
            st_bf4(hp + cb + i*128, h0, h1, h2, h3);
        }
    }
}

// ---------------- K1b: global pool sums per (b, c) ----------------------------
// grid (8, 4, 16): x = pixel slice (512 px), y = channel group (128), z = batch
__global__ void k_gp() {
    int b = blockIdx.z, cg = blockIdx.y, ps = blockIdx.x;
    int t = threadIdx.x;
    int c = cg * 128 + (t & 127);
    int pr = t >> 7;  // 0 or 1
    const __nv_bfloat16* hp = g_h + ((size_t)b*4096 + (size_t)ps*512) * DIMC + c;
    float s = 0.f;
    for (int i = pr; i < 512; i += 2) s += __bfloat162float(hp[(size_t)i * DIMC]);
    __shared__ float sd[256];
    sd[t] = s;
    __syncthreads();
    if (t < 128) atomicAdd(&g_gp[b*DIMC + c], sd[t] + sd[t + 128]);
}

// ---------------- K2: spatial + residual1 + LN2 + row L2 norm -----------------
// writes x2 (fp32) into d_out, writes g_an (bf16), zeroes g_rowsq
__global__ void k_spatial(const float* __restrict__ x, const float* __restrict__ alpha,
                          const float* __restrict__ w2, const float* __restrict__ b2,
                          const float* __restrict__ gamma, float* __restrict__ out) {
    int rowid = blockIdx.x;            // b*64 + y
    int b = rowid >> 6, y = rowid & 63;
    int warp = threadIdx.x >> 5, lane = threadIdx.x & 31;
    int cb = lane * 4;
    float4 av[4], wv[4], bv[4], gv[4], gpv[4];
#pragma unroll
    for (int i = 0; i < 4; i++) {
        av[i] = *(const float4*)(alpha + cb + i*128);
        wv[i] = *(const float4*)(w2 + cb + i*128);
        bv[i] = *(const float4*)(b2 + cb + i*128);
        gv[i] = *(const float4*)(gamma + cb + i*128);
        const float4 gp4 = *(const float4*)(g_gp + b*DIMC + cb + i*128);
        gpv[i] = make_float4(gp4.x*(1.f/4096.f), gp4.y*(1.f/4096.f),
                             gp4.z*(1.f/4096.f), gp4.w*(1.f/4096.f));
    }
    for (int px = 0; px < 8; ++px) {
        int xc = warp * 8 + px;
        size_t p = (size_t)rowid * 64 + xc;
        const __nv_bfloat16* hC = g_h + p * DIMC;
        bool hasU = (y > 0), hasD = (y < 63), hasL = (xc > 0), hasR = (xc < 63);
        const float4* xp = (const float4*)(x + p * DIMC);
        float4 v[4];  // holds x2
        float s = 0.f, sq = 0.f;
#pragma unroll
        for (int i = 0; i < 4; i++) {
            int off = cb + i*128;
            float4 c4 = ld_bf4(hC + off);
            float4 u4 = hasU ? ld_bf4(hC - 64*DIMC + off) : make_float4(0,0,0,0);
            float4 d4 = hasD ? ld_bf4(hC + 64*DIMC + off) : make_float4(0,0,0,0);
            float4 l4 = hasL ? ld_bf4(hC - DIMC + off)    : make_float4(0,0,0,0);
            float4 r4 = hasR ? ld_bf4(hC + DIMC + off)    : make_float4(0,0,0,0);
            float4 fe;
            fe.x = fabsf(c4.x-u4.x)+fabsf(c4.x-d4.x)+fabsf(c4.x-l4.x)+fabsf(c4.x-r4.x);
            fe.y = fabsf(c4.y-u4.y)+fabsf(c4.y-d4.y)+fabsf(c4.y-l4.y)+fabsf(c4.y-r4.y);
            fe.z = fabsf(c4.z-u4.z)+fabsf(c4.z-d4.z)+fabsf(c4.z-l4.z)+fabsf(c4.z-r4.z);
            fe.w = fabsf(c4.w-u4.w)+fabsf(c4.w-d4.w)+fabsf(c4.w-l4.w)+fabsf(c4.w-r4.w);
            float4 sp;
            sp.x = fe.x*av[i].x + gpv[i].x*(1.f-av[i].x);
            sp.y = fe.y*av[i].y + gpv[i].y*(1.f-av[i].y);
            sp.z = fe.z*av[i].z + gpv[i].z*(1.f-av[i].z);
            sp.w = fe.w*av[i].w + gpv[i].w*(1.f-av[i].w);
            float4 xv = xp[lane + i*32];
            v[i].x = xv.x + gv[i].x*sp.x;
            v[i].y = xv.y + gv[i].y*sp.y;
            v[i].z = xv.z + gv[i].z*sp.z;
            v[i].w = xv.w + gv[i].w*sp.w;
            s  += v[i].x + v[i].y + v[i].z + v[i].w;
            sq += v[i].x*v[i].x + v[i].y*v[i].y + v[i].z*v[i].z + v[i].w*v[i].w;
        }
        s = wredsum(s); sq = wredsum(sq);
        float m = s * (1.f/512.f);
        float var = sq * (1.f/512.f) - m*m;
        float rstd = rsqrtf(var + 1e-5f);
        // layernorm2 output + its row L2 norm
        float h2v[16];
        float ss = 0.f;
#pragma unroll
        for (int i = 0; i < 4; i++) {
            h2v[i*4+0] = (v[i].x - m)*rstd*wv[i].x + bv[i].x;
            h2v[i*4+1] = (v[i].y - m)*rstd*wv[i].y + bv[i].y;
            h2v[i*4+2] = (v[i].z - m)*rstd*wv[i].z + bv[i].z;
            h2v[i*4+3] = (v[i].w - m)*rstd*wv[i].w + bv[i].w;
            ss += h2v[i*4+0]*h2v[i*4+0] + h2v[i*4+1]*h2v[i*4+1]
                + h2v[i*4+2]*h2v[i*4+2] + h2v[i*4+3]*h2v[i*4+3];
        }
        ss = wredsum(ss);
        float inv = 1.f / fmaxf(sqrtf(ss), 1e-12f);
        float4* op = (float4*)(out + p * DIMC);
        __nv_bfloat16* ap = g_an + p * DIMC;
#pragma unroll
        for (int i = 0; i < 4; i++) {
            op[lane + i*32] = v[i];
            st_bf4(ap + cb + i*128, h2v[i*4+0]*inv, h2v[i*4+1]*inv,
                                    h2v[i*4+2]*inv, h2v[i*4+3]*inv);
        }
        if (lane == 0) g_rowsq[p] = 0.f;
    }
}

// ---------------- GEMM: bf16 mma.sync, 128x128x32 tiles, 2-stage cp.async -----
#define BM 128
#define BN 128
#define BK 32
#define ASTR 40   // padded A smem stride (conflict-free ldmatrix)
#define BSTR 136  // padded B smem stride

__device__ __forceinline__ void cp_async16(void* smem, const void* g) {
    uint32_t s = (uint32_t)__cvta_generic_to_shared(smem);
    asm volatile("cp.async.cg.shared.global [%0], [%1], 16;\n" :: "r"(s), "l"(g));
}
#define CP_COMMIT() asm volatile("cp.async.commit_group;\n")
#define CP_WAIT0()  asm volatile("cp.async.wait_group 0;\n")

#define MMA16816(d, a, b0v, b1v)                                           \
    asm volatile(                                                          \
        "mma.sync.aligned.m16n8k16.row.col.f32.bf16.bf16.f32 "             \
        "{%0,%1,%2,%3},{%4,%5,%6,%7},{%8,%9},{%0,%1,%2,%3};\n"             \
        : "+f"(d[0]), "+f"(d[1]), "+f"(d[2]), "+f"(d[3])                   \
        : "r"(a[0]), "r"(a[1]), "r"(a[2]), "r"(a[3]), "r"(b0v), "r"(b1v))

// EPI = 1: GEMM1 (A=g_an [M,512], B=g_win [512,1024]) -> gelu -> g_hidden + rowsq
// EPI = 2: GEMM2 (A=g_hidden [M,1024], B=g_wout [1024,512]) -> out += gamma*..*rsqrt
template <int EPI>
__global__ __launch_bounds__(256) void k_gemm(const float* __restrict__ scale,
                                              const float* __restrict__ gamma,
                                              float* __restrict__ outp) {
    const __nv_bfloat16* __restrict__ A = (EPI == 1) ? g_an : g_hidden;
    const __nv_bfloat16* __restrict__ B = (EPI == 1) ? g_win : g_wout;
    const int K = (EPI == 1) ? DIMC : HIDC;
    const int N = (EPI == 1) ? HIDC : DIMC;

    __shared__ __align__(16) __nv_bfloat16 As[2][BM][ASTR];
    __shared__ __align__(16) __nv_bfloat16 Bs[2][BK][BSTR];

    int tid = threadIdx.x;
    int bm = blockIdx.y * BM, bn = blockIdx.x * BN;
    int wid = tid >> 5, lane = tid & 31;
    int wr = wid & 3, wc = wid >> 2;  // warp tile: 32 (m) x 64 (n)

    int ar = tid >> 2, ac = (tid & 3) * 8;   // A load map: rows ar, ar+64
    int br = tid >> 4, bc = (tid & 15) * 8;  // B load map: rows br, br+16

    float acc[2][8][4];
#pragma unroll
    for (int mi = 0; mi < 2; mi++)
#pragma unroll
        for (int ni = 0; ni < 8; ni++)
#pragma unroll
            for (int q = 0; q < 4; q++) acc[mi][ni][q] = 0.f;

    const int nkt = K / BK;
    // prefetch tile 0
    {
        const __nv_bfloat16* ap0 = A + (size_t)(bm + ar) * K + ac;
        cp_async16(&As[0][ar][ac], ap0);
        cp_async16(&As[0][ar + 64][ac], ap0 + (size_t)64 * K);
        const __nv_bfloat16* bp0 = B + (size_t)br * N + bn + bc;
        cp_async16(&Bs[0][br][bc], bp0);
        cp_async16(&Bs[0][br + 16][bc], bp0 + (size_t)16 * N);
    }
    CP_COMMIT();

    for (int kt = 0; kt < nkt; ++kt) {
        CP_WAIT0();
        __syncthreads();
        if (kt + 1 < nkt) {
            int k0 = (kt + 1) * BK;
            int st = (kt + 1) & 1;
            const __nv_bfloat16* ap0 = A + (size_t)(bm + ar) * K + k0 + ac;
            cp_async16(&As[st][ar][ac], ap0);
            cp_async16(&As[st][ar + 64][ac], ap0 + (size_t)64 * K);
            const __nv_bfloat16* bp0 = B + (size_t)(k0 + br) * N + bn + bc;
            cp_async16(&Bs[st][br][bc], bp0);
            cp_async16(&Bs[st][br + 16][bc], bp0 + (size_t)16 * N);
        }
        CP_COMMIT();
        int st = kt & 1;
#pragma unroll
        for (int ks = 0; ks < 2; ++ks) {
            uint32_t a[2][4], bf[4][4];
#pragma unroll
            for (int mi = 0; mi < 2; mi++) {
                int row = wr * 32 + mi * 16 + (lane & 15);
                int col = ks * 16 + ((lane >> 4) << 3);
                uint32_t addr = (uint32_t)__cvta_generic_to_shared(&As[st][row][col]);
                asm volatile("ldmatrix.sync.aligned.m8n8.x4.shared.b16 {%0,%1,%2,%3},[%4];\n"
                             : "=r"(a[mi][0]), "=r"(a[mi][1]), "=r"(a[mi][2]), "=r"(a[mi][3])
                             : "r"(addr));
            }
#pragma unroll
            for (int ni = 0; ni < 4; ni++) {
                int rrow = ks * 16 + ((lane >> 3) & 1) * 8 + (lane & 7);
                int rcol = wc * 64 + ni * 16 + (lane >> 4) * 8;
                uint32_t addr = (uint32_t)__cvta_generic_to_shared(&Bs[st][rrow][rcol]);
                asm volatile("ldmatrix.sync.aligned.m8n8.x4.trans.shared.b16 {%0,%1,%2,%3},[%4];\n"
                             : "=r"(bf[ni][0]), "=r"(bf[ni][1]), "=r"(bf[ni][2]), "=r"(bf[ni][3])
                             : "r"(addr));
            }
#pragma unroll
            for (int mi = 0; mi < 2; mi++)
#pragma unroll
                for (int ni = 0; ni < 4; ni++) {
                    MMA16816(acc[mi][2*ni],     a[mi], bf[ni][0], bf[ni][1]);
                    MMA16816(acc[mi][2*ni + 1], a[mi], bf[ni][2], bf[ni][3]);
                }
        }
        __syncthreads();
    }

    float sc = scale[0];
    if (EPI == 1) {
#pragma unroll
        for (int mi = 0; mi < 2; mi++) {
            int r0 = bm + wr * 32 + mi * 16 + (lane >> 2);
            int r1 = r0 + 8;
            float s0 = 0.f, s1 = 0.f;
#pragma unroll
            for (int ni = 0; ni < 8; ni++) {
                int c = bn + wc * 64 + ni * 8 + (lane & 3) * 2;
                float g0 = gelu_exact(acc[mi][ni][0] * sc);
                float g1 = gelu_exact(acc[mi][ni][1] * sc);
                float g2 = gelu_exact(acc[mi][ni][2] * sc);
                float g3 = gelu_exact(acc[mi][ni][3] * sc);
                __nv_bfloat162 p0 = __floats2bfloat162_rn(g0, g1);
                __nv_bfloat162 p1 = __floats2bfloat162_rn(g2, g3);
                *(__nv_bfloat162*)(g_hidden + (size_t)r0 * HIDC + c) = p0;
                *(__nv_bfloat162*)(g_hidden + (size_t)r1 * HIDC + c) = p1;
                s0 += g0*g0 + g1*g1;
                s1 += g2*g2 + g3*g3;
            }
            s0 += __shfl_xor_sync(0xffffffffu, s0, 1);
            s0 += __shfl_xor_sync(0xffffffffu, s0, 2);
            s1 += __shfl_xor_sync(0xffffffffu, s1, 1);
            s1 += __shfl_xor_sync(0xffffffffu, s1, 2);
            if ((lane & 3) == 0) {
                atomicAdd(&g_rowsq[r0], s0);
                atomicAdd(&g_rowsq[r1], s1);
            }
        }
    } else {
#pragma unroll
        for (int mi = 0; mi < 2; mi++) {
            int r0 = bm + wr * 32 + mi * 16 + (lane >> 2);
            int r1 = r0 + 8;
            float inv0 = 1.f / fmaxf(sqrtf(g_rowsq[r0]), 1e-12f);
            float inv1 = 1.f / fmaxf(sqrtf(g_rowsq[r1]), 1e-12f);
#pragma unroll
            for (int ni = 0; ni < 8; ni++) {
                int c = bn + wc * 64 + ni * 8 + (lane & 3) * 2;
                float ga0 = gamma[c], ga1 = gamma[c + 1];
                size_t i00 = (size_t)r0 * DIMC + c;
                size_t i10 = (size_t)r1 * DIMC + c;
                outp[i00]     += ga0 * acc[mi][ni][0] * sc * inv0;
                outp[i00 + 1] += ga1 * acc[mi][ni][1] * sc * inv0;
                outp[i10]     += ga0 * acc[mi][ni][2] * sc * inv1;
                outp[i10 + 1] += ga1 * acc[mi][ni][3] * sc * inv1;
            }
        }
    }
}

// ---------------- launch ------------------------------------------------------
extern "C" void kernel_launch(void* const* d_in, const int* in_sizes, int n_in,
                              void* d_out, int out_size) {
    const float* x     = (const float*)d_in[0];
    const float* n1w   = (const float*)d_in[1];
    const float* n1b   = (const float*)d_in[2];
    const float* alpha = (const float*)d_in[3];
    const float* n2w   = (const float*)d_in[4];
    const float* n2b   = (const float*)d_in[5];
    const float* pin   = (const float*)d_in[6];
    const float* pout  = (const float*)d_in[7];
    const float* s_in  = (const float*)d_in[8];
    const float* s_out = (const float*)d_in[9];
    const float* gamma = (const float*)d_in[10];
    float* out = (float*)d_out;

    k_norm_win<<<HIDC / 256, 256>>>(pin);
    k_norm_wout<<<DIMC / 256, 256>>>(pout);
    k_ln1<<<NBATCH * HH, 256>>>(x, n1w, n1b);
    k_gp<<<dim3(8, 4, NBATCH), 256>>>();
    k_spatial<<<NBATCH * HH, 256>>>(x, alpha, n2w, n2b, gamma, out);
    k_gemm<1><<<dim3(HIDC / BN, NPIX / BM), 256>>>(s_in, nullptr, nullptr);
    k_gemm<2><<<dim3(DIMC / BN, NPIX / BM), 256>>>(s_out, gamma, out);
}